// round 4
// baseline (speedup 1.0000x reference)
#include <cuda_runtime.h>

// EncodecQuantizer RVQ: x [B,T,D] f32, embed [NQ,K,D] f32 -> codes [NQ,B*T],
// written as float32 (harness __output__ dtype confirmed float in R3).
#define BB    16
#define TT    4096
#define DD    128
#define NQ    8
#define KK    1024
#define NTOK  (BB * TT)          // 65536
#define CHUNK 64                 // codes staged in smem per iteration
#define BLK   128                // threads per block == tokens per block
#define WIN   16                 // near-tie candidate ring size
#define EPS   1.0e-2f            // fp32 distance noise window (>> error bound)

// ||e_k||^2 per (stage, code); recomputed every launch (deterministic).
__device__ float g_norms[NQ * KK];

__global__ void norms_kernel(const float* __restrict__ embed) {
    int k = blockIdx.x * blockDim.x + threadIdx.x;
    if (k >= NQ * KK) return;
    const float* e = embed + (size_t)k * DD;
    float s = 0.0f;
#pragma unroll
    for (int i = 0; i < DD; i++) s = fmaf(e[i], e[i], s);
    g_norms[k] = s;
}

// Exact (fp64) distance 2*<r,e> - ||e||^2 for one candidate codeword.
// fp32*fp32 products are exact in fp64; 128-term fp64 sums are ~2^-53 accurate,
// so the argmax over these matches exact arithmetic.
__device__ __forceinline__ double dist_exact(const float4* __restrict__ rr,
                                             const float* __restrict__ e) {
    double dot = 0.0, nrm = 0.0;
    const float4* ev = reinterpret_cast<const float4*>(e);
#pragma unroll
    for (int j = 0; j < DD / 4; j++) {
        float4 v = ev[j];
        float4 r = rr[j];
        dot += (double)r.x * (double)v.x + (double)r.y * (double)v.y +
               (double)r.z * (double)v.z + (double)r.w * (double)v.w;
        nrm += (double)v.x * (double)v.x + (double)v.y * (double)v.y +
               (double)v.z * (double)v.z + (double)v.w * (double)v.w;
    }
    return 2.0 * dot - nrm;
}

// ---------------------------------------------------------------------------
// One thread owns one token; residual lives in registers across all 8 stages.
// Codebook chunks staged via smem (warp-broadcast reads). Near-tie candidates
// (within EPS of fp32 best) are re-checked in fp64 for an exact argmax.
// ---------------------------------------------------------------------------
__global__ void __launch_bounds__(BLK)
rvq_kernel(const float* __restrict__ x,
           const float* __restrict__ embed,
           float* __restrict__ codes) {
    __shared__ __align__(16) float sm[CHUNK * DD];   // 32 KB codeword chunk
    __shared__ __align__(16) float smn[CHUNK];       // chunk norms

    const int tid = threadIdx.x;
    const int tok = blockIdx.x * BLK + tid;

    float4 rr[DD / 4];
    {
        const float4* xr = reinterpret_cast<const float4*>(x + (size_t)tok * DD);
#pragma unroll
        for (int i = 0; i < DD / 4; i++) rr[i] = xr[i];
    }

    for (int s = 0; s < NQ; s++) {
        const float* es = embed + (size_t)s * KK * DD;
        float bestDist = -3.402823466e+38f;  // -FLT_MAX
        float dwin[WIN];
        int   kwin[WIN];
        int   nw = 0;

        for (int c = 0; c < KK / CHUNK; c++) {
            __syncthreads();
            {
                const float4* eg = reinterpret_cast<const float4*>(
                    es + (size_t)c * CHUNK * DD);
                float4* smv = reinterpret_cast<float4*>(sm);
#pragma unroll
                for (int i = 0; i < (CHUNK * DD / 4) / BLK; i++)
                    smv[tid + i * BLK] = eg[tid + i * BLK];
                if (tid < CHUNK)
                    smn[tid] = g_norms[s * KK + c * CHUNK + tid];
            }
            __syncthreads();

#pragma unroll 1
            for (int k2 = 0; k2 < CHUNK; k2 += 2) {
                float4 a0 = make_float4(0.f, 0.f, 0.f, 0.f);
                float4 a1 = make_float4(0.f, 0.f, 0.f, 0.f);
                const float4* e0 =
                    reinterpret_cast<const float4*>(sm + (k2 + 0) * DD);
                const float4* e1 =
                    reinterpret_cast<const float4*>(sm + (k2 + 1) * DD);
#pragma unroll
                for (int j = 0; j < DD / 4; j++) {
                    float4 v0 = e0[j];
                    float4 v1 = e1[j];
                    a0.x = fmaf(rr[j].x, v0.x, a0.x);
                    a0.y = fmaf(rr[j].y, v0.y, a0.y);
                    a0.z = fmaf(rr[j].z, v0.z, a0.z);
                    a0.w = fmaf(rr[j].w, v0.w, a0.w);
                    a1.x = fmaf(rr[j].x, v1.x, a1.x);
                    a1.y = fmaf(rr[j].y, v1.y, a1.y);
                    a1.z = fmaf(rr[j].z, v1.z, a1.z);
                    a1.w = fmaf(rr[j].w, v1.w, a1.w);
                }
                float d0 = 2.0f * ((a0.x + a0.y) + (a0.z + a0.w)) - smn[k2 + 0];
                float d1 = 2.0f * ((a1.x + a1.y) + (a1.z + a1.w)) - smn[k2 + 1];
                int kb = c * CHUNK + k2;
                // Ascending-k encounter order; ring push keeps every candidate
                // within EPS of the *running* best. The eventual true argmax
                // can only be evicted by >=WIN later pushes that are themselves
                // within EPS of the final best -- vanishingly improbable.
                if (d0 > bestDist) bestDist = d0;
                if (d0 > bestDist - EPS) {
                    int sl = nw & (WIN - 1);
                    dwin[sl] = d0; kwin[sl] = kb; nw++;
                }
                if (d1 > bestDist) bestDist = d1;
                if (d1 > bestDist - EPS) {
                    int sl = nw & (WIN - 1);
                    dwin[sl] = d1; kwin[sl] = kb + 1; nw++;
                }
            }
        }

        // Exact selection among in-window candidates.
        int   bestK = -1;
        {
            const float thr = bestDist - EPS;
            int m = nw < WIN ? nw : WIN;
            int cnt = 0, onlyK = -1;
            for (int i = 0; i < m; i++)
                if (dwin[i] > thr) { cnt++; onlyK = kwin[i]; }
            if (cnt <= 1) {
                bestK = onlyK;  // single survivor: no re-check needed
            } else {
                double bd = -1.0e308;
                int    bk = KK;
                for (int i = 0; i < m; i++) {
                    if (dwin[i] > thr) {
                        int k = kwin[i];
                        double de = dist_exact(rr, es + (size_t)k * DD);
                        // argmax, first occurrence (lowest index) on exact tie
                        if (de > bd || (de == bd && k < bk)) { bd = de; bk = k; }
                    }
                }
                bestK = bk;
            }
        }

        codes[(size_t)s * NTOK + tok] = (float)bestK;
        const float4* eb =
            reinterpret_cast<const float4*>(es + (size_t)bestK * DD);
#pragma unroll
        for (int i = 0; i < DD / 4; i++) {
            float4 ev = eb[i];
            rr[i].x -= ev.x;
            rr[i].y -= ev.y;
            rr[i].z -= ev.z;
            rr[i].w -= ev.w;
        }
    }
}

extern "C" void kernel_launch(void* const* d_in, const int* in_sizes, int n_in,
                              void* d_out, int out_size) {
    const float* p0 = (const float*)d_in[0];
    const float* p1 = (const float*)d_in[1];
    const float* x;
    const float* embed;
    if (in_sizes[0] > in_sizes[1]) { x = p0; embed = p1; }
    else                           { x = p1; embed = p0; }
    float* codes = (float*)d_out;

    norms_kernel<<<(NQ * KK + 255) / 256, 256>>>(embed);
    rvq_kernel<<<NTOK / BLK, BLK>>>(x, embed, codes);
}

// round 5
// speedup vs baseline: 1.1081x; 1.1081x over previous
#include <cuda_runtime.h>

// EncodecQuantizer RVQ: x [B,T,D] f32, embed [NQ,K,D] f32 -> codes [NQ,B*T],
// written as float32 (harness output dtype confirmed float in R3).
#define BB    16
#define TT    4096
#define DD    128
#define NQ    8
#define KK    1024
#define NTOK  (BB * TT)          // 65536
#define CHUNK 64                 // codes staged in smem per iteration
#define BLK   128                // threads per block == tokens per block
#define WIN   16                 // near-tie candidate ring size
#define EPS   1.0e-2f            // fp32 distance noise window

typedef unsigned long long u64;

// ||e_k||^2 per (stage, code); recomputed every launch (deterministic).
__device__ float g_norms[NQ * KK];

__global__ void norms_kernel(const float* __restrict__ embed) {
    int k = blockIdx.x * blockDim.x + threadIdx.x;
    if (k >= NQ * KK) return;
    const float* e = embed + (size_t)k * DD;
    float s = 0.0f;
#pragma unroll
    for (int i = 0; i < DD; i++) s = fmaf(e[i], e[i], s);
    g_norms[k] = s;
}

// Packed f32x2 FMA: acc.lo += a.lo*b.lo; acc.hi += a.hi*b.hi (Blackwell).
#define FMA2(acc, av, bv) \
    asm("fma.rn.f32x2 %0, %1, %2, %0;" : "+l"(acc) : "l"(av), "l"(bv))

__device__ __forceinline__ float lo32(u64 a) {
    return __uint_as_float((unsigned int)(a & 0xffffffffull));
}
__device__ __forceinline__ float hi32(u64 a) {
    return __uint_as_float((unsigned int)(a >> 32));
}
__device__ __forceinline__ u64 pack2(float lo, float hi) {
    return (u64)__float_as_uint(lo) | ((u64)__float_as_uint(hi) << 32);
}
__device__ __forceinline__ float pair_sum(u64 a) { return lo32(a) + hi32(a); }

// Exact (fp64) distance 2*<r,e> - ||e||^2 (argmax-exact; used only for
// near-tie rechecks).
__device__ __forceinline__ double dist_exact(const u64* __restrict__ rr,
                                             const float* __restrict__ e) {
    double dot = 0.0, nrm = 0.0;
#pragma unroll
    for (int j = 0; j < DD / 2; j++) {
        double r0 = (double)lo32(rr[j]);
        double r1 = (double)hi32(rr[j]);
        double v0 = (double)e[2 * j];
        double v1 = (double)e[2 * j + 1];
        dot += r0 * v0 + r1 * v1;
        nrm += v0 * v0 + v1 * v1;
    }
    return 2.0 * dot - nrm;
}

// ---------------------------------------------------------------------------
// One thread owns one token; residual in 64 packed u64 registers across all
// 8 stages. Codebook chunks staged via smem (warp-broadcast reads). Inner
// loop: 4 codes x packed f32x2 FMA chains. Near-tie candidates re-checked
// in fp64 for an exact argmax.
// ---------------------------------------------------------------------------
__global__ void __launch_bounds__(BLK)
rvq_kernel(const float* __restrict__ x,
           const float* __restrict__ embed,
           float* __restrict__ codes) {
    __shared__ __align__(16) float sm[CHUNK * DD];   // 32 KB codeword chunk
    __shared__ __align__(16) float smn[CHUNK];       // chunk norms

    const int tid = threadIdx.x;
    const int tok = blockIdx.x * BLK + tid;

    u64 rr[DD / 2];
    {
        const ulonglong2* xr =
            reinterpret_cast<const ulonglong2*>(x + (size_t)tok * DD);
#pragma unroll
        for (int i = 0; i < DD / 4; i++) {
            ulonglong2 v = xr[i];
            rr[2 * i]     = v.x;
            rr[2 * i + 1] = v.y;
        }
    }

    for (int s = 0; s < NQ; s++) {
        const float* es = embed + (size_t)s * KK * DD;
        float bestDist = -3.402823466e+38f;  // -FLT_MAX
        float dwin[WIN];
        int   kwin[WIN];
        int   nw = 0;

        for (int c = 0; c < KK / CHUNK; c++) {
            __syncthreads();
            {
                const float4* eg = reinterpret_cast<const float4*>(
                    es + (size_t)c * CHUNK * DD);
                float4* smv = reinterpret_cast<float4*>(sm);
#pragma unroll
                for (int i = 0; i < (CHUNK * DD / 4) / BLK; i++)
                    smv[tid + i * BLK] = eg[tid + i * BLK];
                if (tid < CHUNK)
                    smn[tid] = g_norms[s * KK + c * CHUNK + tid];
            }
            __syncthreads();

            // Scan 64 codes, 4 at a time: 4 independent packed-FMA chains.
#pragma unroll 1
            for (int k4 = 0; k4 < CHUNK; k4 += 4) {
                u64 a0 = 0ull, a1 = 0ull, a2 = 0ull, a3 = 0ull;
                const ulonglong2* e0 =
                    reinterpret_cast<const ulonglong2*>(sm + (k4 + 0) * DD);
                const ulonglong2* e1 =
                    reinterpret_cast<const ulonglong2*>(sm + (k4 + 1) * DD);
                const ulonglong2* e2 =
                    reinterpret_cast<const ulonglong2*>(sm + (k4 + 2) * DD);
                const ulonglong2* e3 =
                    reinterpret_cast<const ulonglong2*>(sm + (k4 + 3) * DD);
#pragma unroll
                for (int j = 0; j < DD / 4; j++) {
                    ulonglong2 v0 = e0[j];
                    ulonglong2 v1 = e1[j];
                    ulonglong2 v2 = e2[j];
                    ulonglong2 v3 = e3[j];
                    FMA2(a0, rr[2 * j], v0.x);
                    FMA2(a1, rr[2 * j], v1.x);
                    FMA2(a2, rr[2 * j], v2.x);
                    FMA2(a3, rr[2 * j], v3.x);
                    FMA2(a0, rr[2 * j + 1], v0.y);
                    FMA2(a1, rr[2 * j + 1], v1.y);
                    FMA2(a2, rr[2 * j + 1], v2.y);
                    FMA2(a3, rr[2 * j + 1], v3.y);
                }
                float d0 = 2.0f * pair_sum(a0) - smn[k4 + 0];
                float d1 = 2.0f * pair_sum(a1) - smn[k4 + 1];
                float d2 = 2.0f * pair_sum(a2) - smn[k4 + 2];
                float d3 = 2.0f * pair_sum(a3) - smn[k4 + 3];
                int kb = c * CHUNK + k4;
                // Ascending-k order; ring keeps candidates within EPS of the
                // running best (cannot evict the true argmax in practice).
                if (d0 > bestDist) bestDist = d0;
                if (d0 > bestDist - EPS) {
                    int sl = nw & (WIN - 1); dwin[sl] = d0; kwin[sl] = kb; nw++;
                }
                if (d1 > bestDist) bestDist = d1;
                if (d1 > bestDist - EPS) {
                    int sl = nw & (WIN - 1); dwin[sl] = d1; kwin[sl] = kb + 1; nw++;
                }
                if (d2 > bestDist) bestDist = d2;
                if (d2 > bestDist - EPS) {
                    int sl = nw & (WIN - 1); dwin[sl] = d2; kwin[sl] = kb + 2; nw++;
                }
                if (d3 > bestDist) bestDist = d3;
                if (d3 > bestDist - EPS) {
                    int sl = nw & (WIN - 1); dwin[sl] = d3; kwin[sl] = kb + 3; nw++;
                }
            }
        }

        // Exact selection among in-window candidates.
        int bestK = -1;
        {
            const float thr = bestDist - EPS;
            int m = nw < WIN ? nw : WIN;
            int cnt = 0, onlyK = -1;
            for (int i = 0; i < m; i++)
                if (dwin[i] > thr) { cnt++; onlyK = kwin[i]; }
            if (cnt <= 1) {
                bestK = onlyK;
            } else {
                double bd = -1.0e308;
                int    bk = KK;
                for (int i = 0; i < m; i++) {
                    if (dwin[i] > thr) {
                        int k = kwin[i];
                        double de = dist_exact(rr, es + (size_t)k * DD);
                        if (de > bd || (de == bd && k < bk)) { bd = de; bk = k; }
                    }
                }
                bestK = bk;
            }
        }

        codes[(size_t)s * NTOK + tok] = (float)bestK;
        const float4* eb =
            reinterpret_cast<const float4*>(es + (size_t)bestK * DD);
#pragma unroll
        for (int i = 0; i < DD / 4; i++) {
            float4 ev = eb[i];
            u64 p0 = rr[2 * i], p1 = rr[2 * i + 1];
            rr[2 * i]     = pack2(lo32(p0) - ev.x, hi32(p0) - ev.y);
            rr[2 * i + 1] = pack2(lo32(p1) - ev.z, hi32(p1) - ev.w);
        }
    }
}

extern "C" void kernel_launch(void* const* d_in, const int* in_sizes, int n_in,
                              void* d_out, int out_size) {
    const float* p0 = (const float*)d_in[0];
    const float* p1 = (const float*)d_in[1];
    const float* x;
    const float* embed;
    if (in_sizes[0] > in_sizes[1]) { x = p0; embed = p1; }
    else                           { x = p1; embed = p0; }
    float* codes = (float*)d_out;

    norms_kernel<<<(NQ * KK + 255) / 256, 256>>>(embed);
    rvq_kernel<<<NTOK / BLK, BLK>>>(x, embed, codes);
}

// round 6
// speedup vs baseline: 1.3387x; 1.2081x over previous
#include <cuda_runtime.h>

// EncodecQuantizer RVQ: x [B,T,D] f32, embed [NQ,K,D] f32 -> codes [NQ,B*T]
// written as float32 (harness output dtype confirmed in R3).
#define BB    16
#define TT    4096
#define DD    128
#define NQ    8
#define KK    1024
#define NTOK  (BB * TT)       // 65536
#define MTILE 128             // tokens per block
#define NTILE 64              // codes per smem tile
#define BLKT  256             // threads per block (16 x 16)
#define RSTR  132             // R smem row stride (floats), pad vs bank conflicts
#define BSTR  68              // B smem row stride (floats)
#define EPS   3.0e-3f         // fp32 near-tie window -> fp64 recheck

typedef unsigned long long u64;

// smem layout (floats): R[128][RSTR] | B[128][BSTR] | bestk[128] (as int)
#define SM_R_FLOATS (DD * RSTR)
#define SM_B_FLOATS (DD * BSTR)
#define SMEM_BYTES  ((SM_R_FLOATS + SM_B_FLOATS + MTILE) * 4)

__device__ float g_norms[NQ * KK];

__global__ void norms_kernel(const float* __restrict__ embed) {
    int k = blockIdx.x * blockDim.x + threadIdx.x;
    if (k >= NQ * KK) return;
    const float* e = embed + (size_t)k * DD;
    float s = 0.0f;
#pragma unroll
    for (int i = 0; i < DD; i++) s = fmaf(e[i], e[i], s);
    g_norms[k] = s;
}

// Packed f32x2 FMA (Blackwell): acc += a * b per 32-bit lane.
#define FMA2(acc, av, bv) \
    asm("fma.rn.f32x2 %0, %1, %2, %0;" : "+l"(acc) : "l"(av), "l"(bv))

__device__ __forceinline__ float lo32(u64 a) {
    return __uint_as_float((unsigned int)(a & 0xffffffffull));
}
__device__ __forceinline__ float hi32(u64 a) {
    return __uint_as_float((unsigned int)(a >> 32));
}
__device__ __forceinline__ u64 dup_lo(u64 v) {
    unsigned int b = (unsigned int)v;
    return (u64)b | ((u64)b << 32);
}
__device__ __forceinline__ u64 dup_hi(u64 v) {
    unsigned int b = (unsigned int)(v >> 32);
    return (u64)b | ((u64)b << 32);
}

// Exact (fp64) distance for a token column of smem R vs codeword e (global).
__device__ double dist_exact_col(const float* __restrict__ R, int tok,
                                 const float* __restrict__ e) {
    double dot = 0.0, nrm = 0.0;
#pragma unroll 4
    for (int d = 0; d < DD; d++) {
        double r = (double)R[d * RSTR + tok];
        double v = (double)__ldg(e + d);
        dot += r * v;
        nrm += v * v;
    }
    return 2.0 * dot - nrm;
}

// ---------------------------------------------------------------------------
// Register-tiled RVQ: block owns 128 tokens (residual tile in smem, [d][tok]).
// Per stage: 16 code tiles of 64 (codebook transposed into smem), each thread
// computes an 8-token x 4-code distance tile via packed-f32x2 rank-1 updates.
// Per-token top-2 is merged across the 16 code lanes by shuffle; near-ties
// (gap <= EPS) are resolved exactly in fp64.
// ---------------------------------------------------------------------------
__global__ void __launch_bounds__(BLKT, 2)
rvq_kernel(const float* __restrict__ x,
           const float* __restrict__ embed,
           float* __restrict__ codes) {
    extern __shared__ float sm[];
    float* R  = sm;                          // [DD][RSTR]
    float* Bt = sm + SM_R_FLOATS;            // [DD][BSTR]
    int*   bk = (int*)(sm + SM_R_FLOATS + SM_B_FLOATS);  // [MTILE]

    const int tid = threadIdx.x;
    const int tx  = tid & 15;     // code-lane
    const int ty  = tid >> 4;     // token-lane
    const int tok0 = blockIdx.x * MTILE;

    // ---- Load x -> R transposed ([d][tok]) ----
    {
        int tok = tid & 127, half = tid >> 7;   // 2 threads per token
        const float4* xr =
            reinterpret_cast<const float4*>(x + (size_t)(tok0 + tok) * DD +
                                            half * 64);
#pragma unroll
        for (int j = 0; j < 16; j++) {
            float4 v = xr[j];
            int d = half * 64 + j * 4;
            R[(d + 0) * RSTR + tok] = v.x;
            R[(d + 1) * RSTR + tok] = v.y;
            R[(d + 2) * RSTR + tok] = v.z;
            R[(d + 3) * RSTR + tok] = v.w;
        }
    }
    __syncthreads();

    for (int s = 0; s < NQ; s++) {
        const float* es = embed + (size_t)s * KK * DD;

        // per-token top-2 (8 tokens per thread, over this thread's codes)
        float d1[8], d2v[8];
        int   k1[8], k2[8];
#pragma unroll
        for (int i = 0; i < 8; i++) {
            d1[i] = -3.402823466e+38f; d2v[i] = -3.402823466e+38f;
            k1[i] = 0; k2[i] = 0;
        }

        for (int t = 0; t < KK / NTILE; t++) {
            __syncthreads();   // previous tile's readers done
            // ---- Load code tile -> Bt transposed ([d][code]) ----
            {
                int code = tid >> 2;      // 0..63
                int dg0  = tid & 3;
                const float* eg = es + (size_t)(t * NTILE + code) * DD;
#pragma unroll
                for (int it = 0; it < 8; it++) {
                    int dg = dg0 + it * 4;            // 0..31
                    float4 v = *reinterpret_cast<const float4*>(eg + dg * 4);
                    int d = dg * 4;
                    Bt[(d + 0) * BSTR + code] = v.x;
                    Bt[(d + 1) * BSTR + code] = v.y;
                    Bt[(d + 2) * BSTR + code] = v.z;
                    Bt[(d + 3) * BSTR + code] = v.w;
                }
            }
            __syncthreads();

            // ---- 8x4 micro-GEMM over K=128 (packed pairs along tokens) ----
            u64 acc[16];
#pragma unroll
            for (int i = 0; i < 16; i++) acc[i] = 0ull;

            const float* ra = R + ty * 8;
            const float* rb = Bt + tx * 4;
#pragma unroll 8
            for (int k = 0; k < DD; k++) {
                ulonglong2 av =
                    *reinterpret_cast<const ulonglong2*>(ra + k * RSTR);
                ulonglong2 av2 =
                    *reinterpret_cast<const ulonglong2*>(ra + k * RSTR + 4);
                ulonglong2 bv =
                    *reinterpret_cast<const ulonglong2*>(rb + k * BSTR);
                u64 b0 = dup_lo(bv.x), b1 = dup_hi(bv.x);
                u64 b2 = dup_lo(bv.y), b3 = dup_hi(bv.y);
                FMA2(acc[0],  av.x,  b0); FMA2(acc[1],  av.x,  b1);
                FMA2(acc[2],  av.x,  b2); FMA2(acc[3],  av.x,  b3);
                FMA2(acc[4],  av.y,  b0); FMA2(acc[5],  av.y,  b1);
                FMA2(acc[6],  av.y,  b2); FMA2(acc[7],  av.y,  b3);
                FMA2(acc[8],  av2.x, b0); FMA2(acc[9],  av2.x, b1);
                FMA2(acc[10], av2.x, b2); FMA2(acc[11], av2.x, b3);
                FMA2(acc[12], av2.y, b0); FMA2(acc[13], av2.y, b1);
                FMA2(acc[14], av2.y, b2); FMA2(acc[15], av2.y, b3);
            }

            // ---- Epilogue: distances + top-2 update (ascending code order) ----
            int kb0 = t * NTILE + tx * 4;
#pragma unroll
            for (int ip = 0; ip < 4; ip++) {
#pragma unroll
                for (int j = 0; j < 4; j++) {
                    u64 a = acc[ip * 4 + j];
                    float nj = __ldg(&g_norms[s * KK + kb0 + j]);
                    float dl = 2.0f * lo32(a) - nj;   // token 2*ip
                    float dh = 2.0f * hi32(a) - nj;   // token 2*ip+1
                    int il = 2 * ip, ih = 2 * ip + 1, kc = kb0 + j;
                    if (dl > d1[il]) {
                        d2v[il] = d1[il]; k2[il] = k1[il];
                        d1[il] = dl; k1[il] = kc;
                    } else if (dl > d2v[il]) { d2v[il] = dl; k2[il] = kc; }
                    if (dh > d1[ih]) {
                        d2v[ih] = d1[ih]; k2[ih] = k1[ih];
                        d1[ih] = dh; k1[ih] = kc;
                    } else if (dh > d2v[ih]) { d2v[ih] = dh; k2[ih] = kc; }
                }
            }
        }

        // ---- Merge top-2 across the 16 code lanes (butterfly) ----
#pragma unroll
        for (int m = 1; m < 16; m <<= 1) {
#pragma unroll
            for (int i = 0; i < 8; i++) {
                float od1 = __shfl_xor_sync(0xffffffffu, d1[i], m);
                int   ok1 = __shfl_xor_sync(0xffffffffu, k1[i], m);
                float od2 = __shfl_xor_sync(0xffffffffu, d2v[i], m);
                int   ok2 = __shfl_xor_sync(0xffffffffu, k2[i], m);
                bool ob = (od1 > d1[i]) || (od1 == d1[i] && ok1 < k1[i]);
                if (ob) {
                    // other's best wins; second = better(our best, other's 2nd)
                    bool sb = (d1[i] > od2) || (d1[i] == od2 && k1[i] < ok2);
                    d2v[i] = sb ? d1[i] : od2;
                    k2[i]  = sb ? k1[i] : ok2;
                    d1[i] = od1; k1[i] = ok1;
                } else {
                    bool sb = (od1 > d2v[i]) || (od1 == d2v[i] && ok1 < k2[i]);
                    if (sb) { d2v[i] = od1; k2[i] = ok1; }
                }
            }
        }

        // ---- Finalize per token (lane tx==0), exact recheck on near-ties ----
        if (tx == 0) {
#pragma unroll 1
            for (int i = 0; i < 8; i++) {
                int tok = ty * 8 + i;
                int kbest = k1[i];
                if (d1[i] - d2v[i] <= EPS) {
                    double e1 = dist_exact_col(R, tok, es + (size_t)k1[i] * DD);
                    double e2 = dist_exact_col(R, tok, es + (size_t)k2[i] * DD);
                    if (e2 > e1 || (e2 == e1 && k2[i] < k1[i])) kbest = k2[i];
                }
                bk[tok] = kbest;
            }
        }
        __syncthreads();

        // ---- Emit codes + residual update ----
        {
            int tok = tid & 127, half = tid >> 7;
            int kb2 = bk[tok];
            if (half == 0)
                codes[(size_t)s * NTOK + tok0 + tok] = (float)kb2;
            const float4* eb = reinterpret_cast<const float4*>(
                es + (size_t)kb2 * DD + half * 64);
#pragma unroll
            for (int j = 0; j < 16; j++) {
                float4 v = eb[j];
                int d = half * 64 + j * 4;
                R[(d + 0) * RSTR + tok] -= v.x;
                R[(d + 1) * RSTR + tok] -= v.y;
                R[(d + 2) * RSTR + tok] -= v.z;
                R[(d + 3) * RSTR + tok] -= v.w;
            }
        }
        __syncthreads();
    }
}

extern "C" void kernel_launch(void* const* d_in, const int* in_sizes, int n_in,
                              void* d_out, int out_size) {
    const float* p0 = (const float*)d_in[0];
    const float* p1 = (const float*)d_in[1];
    const float* x;
    const float* embed;
    if (in_sizes[0] > in_sizes[1]) { x = p0; embed = p1; }
    else                           { x = p1; embed = p0; }
    float* codes = (float*)d_out;

    cudaFuncSetAttribute(rvq_kernel,
                         cudaFuncAttributeMaxDynamicSharedMemorySize,
                         SMEM_BYTES);

    norms_kernel<<<(NQ * KK + 255) / 256, 256>>>(embed);
    rvq_kernel<<<NTOK / MTILE, BLKT, SMEM_BYTES>>>(x, embed, codes);
}